// round 15
// baseline (speedup 1.0000x reference)
#include <cuda_runtime.h>
#include <cuda_fp16.h>
#include <math.h>
#include <stdint.h>

// ---------------- static scratch (no allocations allowed) ----------------
#define NMAX   131072
#define TMAX   1700000

__device__ unsigned g_msgsh[(size_t)TMAX * 32];  // r2|r3 messages, half2 words
__device__ unsigned g_msg1h[(size_t)NMAX * 32];  // per-node r1 messages, half2 words
__device__ int   g_colidx[TMAX];
__device__ int   g_counts[NMAX];
__device__ int   g_cnt1[NMAX];
__device__ int   g_rowptr[NMAX + 1];
__device__ int   g_cursor[NMAX];
__device__ int   g_bsum[512];
__device__ float g_hA[(size_t)NMAX * 64];
__device__ float g_hB[(size_t)NMAX * 64];
__device__ float g_maxmsg[(size_t)NMAX * 64];
__device__ int   g_bounds[257];
__device__ float g_agg[256 * 64];

// packed fp16 weights: word (k2, n) = half2{ W[2*k2][n], W[2*k2+1][n] }
__device__ unsigned g_pWi1[32 * 64],   g_pWo1[32 * 64];
__device__ unsigned g_pWi2[64 * 128],  g_pWo2[64 * 128];
__device__ unsigned g_pWi3[96 * 192],  g_pWo3[96 * 192];
__device__ unsigned g_puWi[64 * 128],  g_puWo[64 * 64];

// ---------------- math helpers ----------------
__device__ __forceinline__ float mishf(float x) {
    if (x > 20.f) return x;
    float e = __expf(x);
    float n = e * (e + 2.f);
    return x * (n / (n + 2.f));
}

__device__ __forceinline__ unsigned pack_h2(float a, float b) {
    __half2 h = __floats2half2_rn(a, b);
    return *reinterpret_cast<unsigned*>(&h);
}

__device__ __forceinline__ void unpack_h2(unsigned w, float& a, float& b) {
    __half2 h = *reinterpret_cast<__half2*>(&w);
    a = __low2float(h);
    b = __high2float(h);
}

// m16n8k16 f16 MMA, fp32 accumulate
__device__ __forceinline__ void mma16(float* c, unsigned a0, unsigned a1, unsigned a2, unsigned a3,
                                      unsigned b0, unsigned b1) {
    asm volatile(
        "mma.sync.aligned.m16n8k16.row.col.f32.f16.f16.f32 "
        "{%0,%1,%2,%3}, {%4,%5,%6,%7}, {%8,%9}, {%0,%1,%2,%3};\n"
        : "+f"(c[0]), "+f"(c[1]), "+f"(c[2]), "+f"(c[3])
        : "r"(a0), "r"(a1), "r"(a2), "r"(a3), "r"(b0), "r"(b1));
}

// ldmatrix x4: loads the full m16n8k16 A fragment (4 regs) from a 16x16 half tile
__device__ __forceinline__ void ldsm4(unsigned& r0, unsigned& r1, unsigned& r2, unsigned& r3,
                                      unsigned addr) {
    asm volatile("ldmatrix.sync.aligned.m8n8.x4.shared.b16 {%0,%1,%2,%3}, [%4];"
                 : "=r"(r0), "=r"(r1), "=r"(r2), "=r"(r3) : "r"(addr));
}

// ---------------- weight pre-packing (1 launch) ----------------
__device__ __forceinline__ unsigned pack_w(const float* __restrict__ W, int N, int j) {
    int k2 = j / N, n = j - k2 * N;
    return pack_h2(W[(2 * k2) * N + n], W[(2 * k2 + 1) * N + n]);
}

__global__ void conv_all_kernel(const float* __restrict__ Wi1, const float* __restrict__ Wo1,
                                const float* __restrict__ Wi2, const float* __restrict__ Wo2,
                                const float* __restrict__ Wi3, const float* __restrict__ Wo3,
                                const float* __restrict__ uWi, const float* __restrict__ uWo)
{
    int i = blockIdx.x * blockDim.x + threadIdx.x;
    if (i < 2048)            g_pWi1[i] = pack_w(Wi1, 64, i);
    else if (i < 4096)       g_pWo1[i - 2048]  = pack_w(Wo1, 64,  i - 2048);
    else if (i < 12288)      g_pWi2[i - 4096]  = pack_w(Wi2, 128, i - 4096);
    else if (i < 20480)      g_pWo2[i - 12288] = pack_w(Wo2, 128, i - 12288);
    else if (i < 38912)      g_pWi3[i - 20480] = pack_w(Wi3, 192, i - 20480);
    else if (i < 57344)      g_pWo3[i - 38912] = pack_w(Wo3, 192, i - 38912);
    else if (i < 65536)      g_puWi[i - 57344] = pack_w(uWi, 128, i - 57344);
    else if (i < 69632)      g_puWo[i - 65536] = pack_w(uWo, 64,  i - 65536);
}

// ---------------- CSR build (r2/r3 only; r1 -> multiplicity counts) ----------------
__global__ void zero_counts_kernel(int n) {
    int i = blockIdx.x * blockDim.x + threadIdx.x;
    if (i < n) { g_counts[i] = 0; g_cnt1[i] = 0; }
}

__global__ void count_all_kernel(const int* __restrict__ a1, int n1,
                                 const int* __restrict__ a2, int n2,
                                 const int* __restrict__ a3, int n3)
{
    int total = n1 + n2 + n3;
    for (int i = blockIdx.x * blockDim.x + threadIdx.x; i < total; i += gridDim.x * blockDim.x) {
        if (i < n2)            atomicAdd(&g_counts[a2[i]], 1);
        else if (i < n2 + n3)  atomicAdd(&g_counts[a3[i - n2]], 1);
        else                   atomicAdd(&g_cnt1[a1[i - n2 - n3]], 1);
    }
}

__global__ void scan_local_kernel(int n) {
    __shared__ int wsum[32];
    int i = blockIdx.x * 1024 + threadIdx.x;
    int lane = threadIdx.x & 31, wid = threadIdx.x >> 5;
    int v = (i < n) ? g_counts[i] : 0;
    int x = v;
    #pragma unroll
    for (int o = 1; o < 32; o <<= 1) {
        int y = __shfl_up_sync(0xFFFFFFFFu, x, o);
        if (lane >= o) x += y;
    }
    if (lane == 31) wsum[wid] = x;
    __syncthreads();
    if (wid == 0) {
        int s = wsum[lane];
        #pragma unroll
        for (int o = 1; o < 32; o <<= 1) {
            int y = __shfl_up_sync(0xFFFFFFFFu, s, o);
            if (lane >= o) s += y;
        }
        wsum[lane] = s;
    }
    __syncthreads();
    int excl = x - v + ((wid > 0) ? wsum[wid - 1] : 0);
    if (i < n) g_rowptr[i] = excl;
    if (threadIdx.x == 1023) g_bsum[blockIdx.x] = excl + v;
}

__global__ void scan_tops_kernel(int nb, int n) {
    __shared__ int sh[512];
    int t = threadIdx.x;
    int v = (t < nb) ? g_bsum[t] : 0;
    sh[t] = v;
    __syncthreads();
    for (int o = 1; o < 512; o <<= 1) {
        int y = (t >= o) ? sh[t - o] : 0;
        __syncthreads();
        sh[t] += y;
        __syncthreads();
    }
    if (t < nb) g_bsum[t] = sh[t] - v;
    if (t == 0) g_rowptr[n] = sh[511];
}

__global__ void scan_add_kernel(int n) {
    int i = blockIdx.x * blockDim.x + threadIdx.x;
    if (i < n) {
        int r = g_rowptr[i] + g_bsum[i >> 10];
        g_rowptr[i] = r;
        g_cursor[i] = r;
    }
}

__global__ void fill_all_kernel(const int* __restrict__ a2, int n2,
                                const int* __restrict__ a3, int n3)
{
    int total = n2 + n3;
    for (int i = blockIdx.x * blockDim.x + threadIdx.x; i < total; i += gridDim.x * blockDim.x) {
        int v = (i < n2) ? a2[i] : a3[i - n2];
        int pos = atomicAdd(&g_cursor[v], 1);
        g_colidx[pos] = i;
    }
}

// ---------------- relation MLP (FP16 MMA, ldmatrix a-frags) ----------------
template <int S, int A, int R, int IDENT>
__global__ void __launch_bounds__(256)
rel_kernel(const float* __restrict__ hext, int hsel,
           const int* __restrict__ atoms, int m,
           const float* __restrict__ bi, const float* __restrict__ bo,
           long long outOffW)
{
    constexpr int BM  = 64;
    constexpr int NT  = S / 32;
    constexpr int KC  = S / 16;
    constexpr int XST = S / 2 + 4;
    constexpr int WST = S + 8;
    constexpr int S4  = S / 4;
    constexpr int PF4 = (2 * S + 255) / 256;

    extern __shared__ unsigned sm[];
    unsigned* xs  = sm;
    unsigned* ws0 = xs + BM * XST;
    unsigned* ws1 = ws0 + 8 * WST;
    int* sidx = (int*)(ws1 + 8 * WST);

    const unsigned* Wip = (R == 1) ? g_pWi1 : (R == 2) ? g_pWi2 : g_pWi3;
    const unsigned* Wop = (R == 1) ? g_pWo1 : (R == 2) ? g_pWo2 : g_pWo3;
    const uint4* Wi4 = (const uint4*)Wip;
    const uint4* Wo4 = (const uint4*)Wop;

    const float* h = (hsel == 0) ? hext : ((hsel == 1) ? g_hA : g_hB);
    unsigned* outw = IDENT ? g_msg1h : (g_msgsh + outOffW);

    const int tid  = threadIdx.x;
    const int lane = tid & 31;
    const int warp = tid >> 5;
    const int rg   = warp & 1;
    const int cg   = warp >> 1;
    const int gid  = lane >> 2;
    const int ctg  = lane & 3;
    const int row0 = blockIdx.x * BM;

    if (!IDENT) {
        if (tid < BM * A) {
            int t = row0 * A + tid;
            sidx[tid] = (t < m * A) ? atoms[t] : 0;
        }
        __syncthreads();
    }

    const float4* h4 = (const float4*)h;
    #pragma unroll
    for (int v = 0; v < S / 16; v++) {
        int u = tid + v * 256;
        int r = u / S4;
        int rem = u - r * S4;
        int node;
        if (IDENT) { node = row0 + r; if (node >= m) node = 0; }
        else       { node = sidx[r * A + (rem >> 4)]; }
        float4 val = h4[(size_t)node * 16 + (rem & 15)];
        ((uint2*)xs)[r * (XST / 2) + rem] = make_uint2(pack_h2(val.x, val.y), pack_h2(val.z, val.w));
    }

    {
        uint4 pre[PF4];
        #pragma unroll
        for (int v = 0; v < PF4; v++) {
            int u = tid + v * 256;
            if (u < 2 * S) pre[v] = Wi4[u];
        }
        #pragma unroll
        for (int v = 0; v < PF4; v++) {
            int u = tid + v * 256;
            if (u < 2 * S) {
                int rr = u / S4, c4 = u - rr * S4;
                ((uint4*)ws0)[rr * (WST / 4) + c4] = pre[v];
            }
        }
    }
    __syncthreads();

    float acc[2][NT][4];
    #pragma unroll
    for (int mt = 0; mt < 2; mt++)
        #pragma unroll
        for (int nt = 0; nt < NT; nt++)
            #pragma unroll
            for (int q = 0; q < 4; q++) acc[mt][nt][q] = 0.f;

    const int cb = cg * (S / 4);

    // ldmatrix lane base addresses for the two 16x16 A tiles
    unsigned asb[2];
    #pragma unroll
    for (int mt = 0; mt < 2; mt++) {
        int arow = rg * 32 + mt * 16 + (lane & 15);
        int ac0  = (lane >> 4) * 4;
        asb[mt] = (unsigned)__cvta_generic_to_shared(xs + arow * XST + ac0);
    }

    unsigned* cur = ws0;
    unsigned* nxt = ws1;

    // ---- GEMM1: acc = x @ Wi ----
    for (int kc = 0; kc < KC; kc++) {
        uint4 pre[PF4];
        if (kc + 1 < KC) {
            #pragma unroll
            for (int v = 0; v < PF4; v++) {
                int u = tid + v * 256;
                if (u < 2 * S) pre[v] = Wi4[(kc + 1) * 2 * S + u];
            }
        }
        {
            unsigned a[2][4];
            ldsm4(a[0][0], a[0][1], a[0][2], a[0][3], asb[0] + kc * 32);
            ldsm4(a[1][0], a[1][1], a[1][2], a[1][3], asb[1] + kc * 32);
            #pragma unroll
            for (int nt = 0; nt < NT; nt++) {
                int bcol = cb + nt * 8 + gid;
                unsigned b0 = cur[ctg * WST + bcol];
                unsigned b1 = cur[(ctg + 4) * WST + bcol];
                mma16(acc[0][nt], a[0][0], a[0][1], a[0][2], a[0][3], b0, b1);
                mma16(acc[1][nt], a[1][0], a[1][1], a[1][2], a[1][3], b0, b1);
            }
        }
        if (kc + 1 < KC) {
            #pragma unroll
            for (int v = 0; v < PF4; v++) {
                int u = tid + v * 256;
                if (u < 2 * S) {
                    int rr = u / S4, c4 = u - rr * S4;
                    ((uint4*)nxt)[rr * (WST / 4) + c4] = pre[v];
                }
            }
        }
        __syncthreads();
        unsigned* tmp = cur; cur = nxt; nxt = tmp;
    }

    #pragma unroll
    for (int mt = 0; mt < 2; mt++) {
        int rA = rg * 32 + mt * 16 + gid;
        #pragma unroll
        for (int nt = 0; nt < NT; nt++) {
            int c0 = cb + nt * 8 + 2 * ctg;
            int wc = (cb >> 1) + nt * 4 + ctg;
            float bi0 = __ldg(&bi[c0]), bi1 = __ldg(&bi[c0 + 1]);
            float bo0 = __ldg(&bo[c0]), bo1 = __ldg(&bo[c0 + 1]);
            unsigned* p0 = &xs[rA * XST + wc];
            unsigned* p1 = &xs[(rA + 8) * XST + wc];
            float x00, x01, x10, x11;
            unpack_h2(*p0, x00, x01);
            unpack_h2(*p1, x10, x11);
            *p0 = pack_h2(mishf(acc[mt][nt][0] + bi0), mishf(acc[mt][nt][1] + bi1));
            *p1 = pack_h2(mishf(acc[mt][nt][2] + bi0), mishf(acc[mt][nt][3] + bi1));
            acc[mt][nt][0] = x00 + bo0;
            acc[mt][nt][1] = x01 + bo1;
            acc[mt][nt][2] = x10 + bo0;
            acc[mt][nt][3] = x11 + bo1;
        }
    }

    {
        uint4 pre[PF4];
        #pragma unroll
        for (int v = 0; v < PF4; v++) {
            int u = tid + v * 256;
            if (u < 2 * S) pre[v] = Wo4[u];
        }
        #pragma unroll
        for (int v = 0; v < PF4; v++) {
            int u = tid + v * 256;
            if (u < 2 * S) {
                int rr = u / S4, c4 = u - rr * S4;
                ((uint4*)ws0)[rr * (WST / 4) + c4] = pre[v];
            }
        }
    }
    __syncthreads();

    // ---- GEMM2: acc += mish(.) @ Wo ----
    cur = ws0; nxt = ws1;
    for (int kc = 0; kc < KC; kc++) {
        uint4 pre[PF4];
        if (kc + 1 < KC) {
            #pragma unroll
            for (int v = 0; v < PF4; v++) {
                int u = tid + v * 256;
                if (u < 2 * S) pre[v] = Wo4[(kc + 1) * 2 * S + u];
            }
        }
        {
            unsigned a[2][4];
            ldsm4(a[0][0], a[0][1], a[0][2], a[0][3], asb[0] + kc * 32);
            ldsm4(a[1][0], a[1][1], a[1][2], a[1][3], asb[1] + kc * 32);
            #pragma unroll
            for (int nt = 0; nt < NT; nt++) {
                int bcol = cb + nt * 8 + gid;
                unsigned b0 = cur[ctg * WST + bcol];
                unsigned b1 = cur[(ctg + 4) * WST + bcol];
                mma16(acc[0][nt], a[0][0], a[0][1], a[0][2], a[0][3], b0, b1);
                mma16(acc[1][nt], a[1][0], a[1][1], a[1][2], a[1][3], b0, b1);
            }
        }
        if (kc + 1 < KC) {
            #pragma unroll
            for (int v = 0; v < PF4; v++) {
                int u = tid + v * 256;
                if (u < 2 * S) {
                    int rr = u / S4, c4 = u - rr * S4;
                    ((uint4*)nxt)[rr * (WST / 4) + c4] = pre[v];
                }
            }
        }
        __syncthreads();
        unsigned* tmp = cur; cur = nxt; nxt = tmp;
    }

    #pragma unroll
    for (int mt = 0; mt < 2; mt++) {
        int rA = row0 + rg * 32 + mt * 16 + gid;
        #pragma unroll
        for (int nt = 0; nt < NT; nt++) {
            int wc = (cb >> 1) + nt * 4 + ctg;
            if (rA < m)
                __stcs(&outw[(size_t)rA * (S / 2) + wc], pack_h2(acc[mt][nt][0], acc[mt][nt][1]));
            if (rA + 8 < m)
                __stcs(&outw[(size_t)(rA + 8) * (S / 2) + wc], pack_h2(acc[mt][nt][2], acc[mt][nt][3]));
        }
    }
}

// ---------------- smooth-max aggregation: two-pass packed fp16 (R11 version) ----------------
__global__ void agg_kernel(int n) {
    int w = (blockIdx.x * blockDim.x + threadIdx.x) >> 5;
    if (w >= n) return;
    int lane = threadIdx.x & 31;
    int s = g_rowptr[w], e = g_rowptr[w + 1];
    int k = g_cnt1[w];

    const float inv12 = 1.f / 12.f;

    if (s == e && k == 0) {
        float r = __logf(1e-16f) * inv12;
        *(float2*)&g_maxmsg[(size_t)w * 64 + 2 * lane] = make_float2(r, r);
        return;
    }

    __half2 mh = __float2half2_rn(-65504.f);
    for (int i = s; i < e; i++) {
        int c = __ldg(&g_colidx[i]);
        unsigned wv = __ldg(&g_msgsh[(size_t)c * 32 + lane]);
        mh = __hmax2(mh, *(__half2*)&wv);
    }
    unsigned w1v = 0;
    if (k > 0) {
        w1v = g_msg1h[(size_t)w * 32 + lane];
        mh = __hmax2(mh, *(__half2*)&w1v);
    }

    const __half2 K2 = __float2half2_rn(17.3123405f);
    float s1a = 0.f, s1b = 0.f, s2a = 0.f, s2b = 0.f;
    int i = s;
    for (; i + 2 <= e; i += 2) {
        int c0 = __ldg(&g_colidx[i]);
        int c1 = __ldg(&g_colidx[i + 1]);
        unsigned v0 = __ldcs(&g_msgsh[(size_t)c0 * 32 + lane]);
        unsigned v1 = __ldcs(&g_msgsh[(size_t)c1 * 32 + lane]);
        __half2 e0 = h2exp2(__hmul2(__hsub2(*(__half2*)&v0, mh), K2));
        __half2 e1 = h2exp2(__hmul2(__hsub2(*(__half2*)&v1, mh), K2));
        float2 f0 = __half22float2(e0);
        float2 f1 = __half22float2(e1);
        s1a += f0.x; s2a += f0.y;
        s1b += f1.x; s2b += f1.y;
    }
    if (i < e) {
        int c0 = __ldg(&g_colidx[i]);
        unsigned v0 = __ldcs(&g_msgsh[(size_t)c0 * 32 + lane]);
        __half2 e0 = h2exp2(__hmul2(__hsub2(*(__half2*)&v0, mh), K2));
        float2 f0 = __half22float2(e0);
        s1a += f0.x; s2a += f0.y;
    }

    float m1 = __low2float(mh), m2 = __high2float(mh);
    float s1 = s1a + s1b, s2 = s2a + s2b;

    if (k > 0) {
        float kf = (float)k;
        float y1, y2;
        unpack_h2(w1v, y1, y2);
        s1 += kf * exp2f(17.3123405f * (y1 - m1));
        s2 += kf * exp2f(17.3123405f * (y2 - m2));
    }

    float r1v = __logf(1e-16f + s1) * inv12 + m1;
    float r2v = __logf(1e-16f + s2) * inv12 + m2;
    *(float2*)&g_maxmsg[(size_t)w * 64 + 2 * lane] = make_float2(r1v, r2v);
}

// ---------------- update MLP (FP16 MMA, ldmatrix a-frags) ----------------
__global__ void __launch_bounds__(256)
update_kernel(const float* __restrict__ hext, int hinsel, int houtsel, int n,
              const float* __restrict__ bi, const float* __restrict__ bo)
{
    constexpr int XST = 68;
    constexpr int WST = 136;
    extern __shared__ unsigned sm[];
    unsigned* xs  = sm;
    unsigned* ws0 = xs + 64 * XST;
    unsigned* ws1 = ws0 + 8 * WST;

    const float* hin = (hinsel == 0) ? hext : ((hinsel == 1) ? g_hA : g_hB);
    float* hout = (houtsel == 1) ? g_hA : g_hB;

    const uint4* Wi4 = (const uint4*)g_puWi;
    const uint4* Wo4 = (const uint4*)g_puWo;

    const int tid  = threadIdx.x;
    const int lane = tid & 31;
    const int warp = tid >> 5;
    const int rg   = warp & 1;
    const int cg   = warp >> 1;
    const int gid  = lane >> 2;
    const int ctg  = lane & 3;
    const int row0 = blockIdx.x * 64;

    const float4* h4 = (const float4*)hin;
    const float4* mm4 = (const float4*)g_maxmsg;
    #pragma unroll
    for (int v = 0; v < 8; v++) {
        int u = tid + v * 256;
        int r = u >> 5, c4 = u & 31;
        float4 val = (c4 < 16) ? mm4[(size_t)(row0 + r) * 16 + c4]
                               : h4[(size_t)(row0 + r) * 16 + (c4 - 16)];
        ((uint2*)xs)[r * (XST / 2) + c4] = make_uint2(pack_h2(val.x, val.y), pack_h2(val.z, val.w));
    }
    {
        uint4 pre = Wi4[tid];
        ((uint4*)ws0)[(tid >> 5) * 34 + (tid & 31)] = pre;
    }
    __syncthreads();

    float acc[2][4][4];
    #pragma unroll
    for (int mt = 0; mt < 2; mt++)
        #pragma unroll
        for (int nt = 0; nt < 4; nt++)
            #pragma unroll
            for (int q = 0; q < 4; q++) acc[mt][nt][q] = 0.f;

    // ldmatrix lane base addresses
    unsigned asb[2];
    #pragma unroll
    for (int mt = 0; mt < 2; mt++) {
        int arow = rg * 32 + mt * 16 + (lane & 15);
        int ac0  = (lane >> 4) * 4;
        asb[mt] = (unsigned)__cvta_generic_to_shared(xs + arow * XST + ac0);
    }

    unsigned* cur = ws0;
    unsigned* nxt = ws1;
    for (int kc = 0; kc < 8; kc++) {
        uint4 pre;
        if (kc + 1 < 8) pre = Wi4[(kc + 1) * 256 + tid];
        {
            unsigned a[2][4];
            ldsm4(a[0][0], a[0][1], a[0][2], a[0][3], asb[0] + kc * 32);
            ldsm4(a[1][0], a[1][1], a[1][2], a[1][3], asb[1] + kc * 32);
            #pragma unroll
            for (int nt = 0; nt < 4; nt++) {
                int bcol = cg * 32 + nt * 8 + gid;
                unsigned b0 = cur[ctg * WST + bcol];
                unsigned b1 = cur[(ctg + 4) * WST + bcol];
                mma16(acc[0][nt], a[0][0], a[0][1], a[0][2], a[0][3], b0, b1);
                mma16(acc[1][nt], a[1][0], a[1][1], a[1][2], a[1][3], b0, b1);
            }
        }
        if (kc + 1 < 8) {
            ((uint4*)nxt)[(tid >> 5) * 34 + (tid & 31)] = pre;
        }
        __syncthreads();
        unsigned* tmp = cur; cur = nxt; nxt = tmp;
    }

    float acc2[2][2][4];
    #pragma unroll
    for (int mt = 0; mt < 2; mt++) {
        int rA = rg * 32 + mt * 16 + gid;
        #pragma unroll
        for (int nt = 0; nt < 2; nt++) {
            int c0 = cg * 16 + nt * 8 + 2 * ctg;
            int wc = 32 + cg * 8 + nt * 4 + ctg;
            float bo0 = __ldg(&bo[c0]), bo1 = __ldg(&bo[c0 + 1]);
            float x00, x01, x10, x11;
            unpack_h2(xs[rA * XST + wc], x00, x01);
            unpack_h2(xs[(rA + 8) * XST + wc], x10, x11);
            acc2[mt][nt][0] = x00 + bo0;
            acc2[mt][nt][1] = x01 + bo1;
            acc2[mt][nt][2] = x10 + bo0;
            acc2[mt][nt][3] = x11 + bo1;
        }
    }
    __syncthreads();

    #pragma unroll
    for (int mt = 0; mt < 2; mt++) {
        int rA = rg * 32 + mt * 16 + gid;
        #pragma unroll
        for (int nt = 0; nt < 4; nt++) {
            int c0 = cg * 32 + nt * 8 + 2 * ctg;
            int wc = cg * 16 + nt * 4 + ctg;
            float bi0 = __ldg(&bi[c0]), bi1 = __ldg(&bi[c0 + 1]);
            xs[rA * XST + wc]       = pack_h2(mishf(acc[mt][nt][0] + bi0), mishf(acc[mt][nt][1] + bi1));
            xs[(rA + 8) * XST + wc] = pack_h2(mishf(acc[mt][nt][2] + bi0), mishf(acc[mt][nt][3] + bi1));
        }
    }

    {
        uint4 preW;
        if (tid < 128) preW = Wo4[tid];
        __syncthreads();
        if (tid < 128) ((uint4*)ws0)[(tid >> 4) * 34 + (tid & 15)] = preW;
    }
    __syncthreads();

    cur = ws0; nxt = ws1;
    for (int kc = 0; kc < 8; kc++) {
        uint4 pre;
        if (kc + 1 < 8 && tid < 128) pre = Wo4[(kc + 1) * 128 + tid];
        {
            unsigned a[2][4];
            ldsm4(a[0][0], a[0][1], a[0][2], a[0][3], asb[0] + kc * 32);
            ldsm4(a[1][0], a[1][1], a[1][2], a[1][3], asb[1] + kc * 32);
            #pragma unroll
            for (int nt = 0; nt < 2; nt++) {
                int bcol = cg * 16 + nt * 8 + gid;
                unsigned b0 = cur[ctg * WST + bcol];
                unsigned b1 = cur[(ctg + 4) * WST + bcol];
                mma16(acc2[0][nt], a[0][0], a[0][1], a[0][2], a[0][3], b0, b1);
                mma16(acc2[1][nt], a[1][0], a[1][1], a[1][2], a[1][3], b0, b1);
            }
        }
        if (kc + 1 < 8 && tid < 128) {
            ((uint4*)nxt)[(tid >> 4) * 34 + (tid & 15)] = pre;
        }
        __syncthreads();
        unsigned* tmp = cur; cur = nxt; nxt = tmp;
    }

    #pragma unroll
    for (int mt = 0; mt < 2; mt++) {
        int rA = row0 + rg * 32 + mt * 16 + gid;
        #pragma unroll
        for (int nt = 0; nt < 2; nt++) {
            int c0 = cg * 16 + nt * 8 + 2 * ctg;
            if (rA < n)
                *(float2*)&hout[(size_t)rA * 64 + c0] = make_float2(acc2[mt][nt][0], acc2[mt][nt][1]);
            if (rA + 8 < n)
                *(float2*)&hout[(size_t)(rA + 8) * 64 + c0] = make_float2(acc2[mt][nt][2], acc2[mt][nt][3]);
        }
    }
}

// ---------------- readout ----------------
__global__ void bounds_kernel(const int* __restrict__ tok, int B) {
    if (threadIdx.x == 0) {
        int c = 0;
        g_bounds[0] = 0;
        for (int i = 0; i < B; i++) { c += tok[i]; g_bounds[i + 1] = c; }
    }
}

__global__ void segsum_kernel() {
    int b = blockIdx.x;
    int s = g_bounds[b], e = g_bounds[b + 1];
    int f = threadIdx.x & 63, g = threadIdx.x >> 6;
    float a = 0.f;
    for (int r = s + g; r < e; r += 4) a += g_hB[(size_t)r * 64 + f];
    __shared__ float red[256];
    red[threadIdx.x] = a;
    __syncthreads();
    if (g == 0) g_agg[b * 64 + f] = red[f] + red[64 + f] + red[128 + f] + red[192 + f];
}

__global__ void heads_kernel(const float* __restrict__ vWi, const float* __restrict__ vbi,
                             const float* __restrict__ vWo, const float* __restrict__ vbo,
                             const float* __restrict__ dWi, const float* __restrict__ dbi,
                             const float* __restrict__ dWo, const float* __restrict__ dbo,
                             float* __restrict__ out, int B)
{
    int b = blockIdx.x, o = threadIdx.x;
    __shared__ float a[64];
    __shared__ float red[64];
    a[o] = g_agg[b * 64 + o];
    __syncthreads();

    float t = vbi[o];
    for (int i = 0; i < 64; i++) t = fmaf(a[i], vWi[i * 64 + o], t);
    red[o] = mishf(t) * vWo[o];
    __syncthreads();
    for (int s = 32; s > 0; s >>= 1) {
        if (o < s) red[o] += red[o + s];
        __syncthreads();
    }
    if (o == 0) out[b] = red[0] + vbo[0];
    __syncthreads();

    t = dbi[o];
    for (int i = 0; i < 64; i++) t = fmaf(a[i], dWi[i * 64 + o], t);
    red[o] = mishf(t) * dWo[o];
    __syncthreads();
    for (int s = 32; s > 0; s >>= 1) {
        if (o < s) red[o] += red[o + s];
        __syncthreads();
    }
    if (o == 0) out[B + b] = red[0] + dbo[0];
}

// ---------------- host launch ----------------
static inline int smem_rel(int S, int A) {
    return (64 * (S / 2 + 4) + 16 * (S + 8)) * 4 + 64 * A * 4;
}

extern "C" void kernel_launch(void* const* d_in, const int* in_sizes, int n_in,
                              void* d_out, int out_size)
{
    if (n_in < 29) return;
    const float* h0  = (const float*)d_in[0];
    const int*   a1  = (const int*)d_in[1];  int n1 = in_sizes[1];
    const int*   a2  = (const int*)d_in[2];  int n2 = in_sizes[2];
    const int*   a3  = (const int*)d_in[3];  int n3 = in_sizes[3];
    const int*   tok = (const int*)d_in[4];  int B  = in_sizes[4];
    const float* Wi1 = (const float*)d_in[5],  *bi1 = (const float*)d_in[6];
    const float* Wo1 = (const float*)d_in[7],  *bo1 = (const float*)d_in[8];
    const float* Wi2 = (const float*)d_in[9],  *bi2 = (const float*)d_in[10];
    const float* Wo2 = (const float*)d_in[11], *bo2 = (const float*)d_in[12];
    const float* Wi3 = (const float*)d_in[13], *bi3 = (const float*)d_in[14];
    const float* Wo3 = (const float*)d_in[15], *bo3 = (const float*)d_in[16];
    const float* uWi = (const float*)d_in[17], *ubi = (const float*)d_in[18];
    const float* uWo = (const float*)d_in[19], *ubo = (const float*)d_in[20];
    const float* vWi = (const float*)d_in[21], *vbi = (const float*)d_in[22];
    const float* vWo = (const float*)d_in[23], *vbo = (const float*)d_in[24];
    const float* dWi = (const float*)d_in[25], *dbi = (const float*)d_in[26];
    const float* dWo = (const float*)d_in[27], *dbo = (const float*)d_in[28];
    float* out = (float*)d_out;

    int N = in_sizes[0] / 64;
    int m2 = n2 / 2, m3 = n3 / 3;
    int nb = (N + 1023) / 1024;

    const int SM1 = smem_rel(64, 1);
    const int SM2 = smem_rel(128, 2);
    const int SM3 = smem_rel(192, 3);
    const int SMU = (64 * 68 + 16 * 136) * 4;

    cudaFuncSetAttribute(rel_kernel<64, 1, 1, 1>,  cudaFuncAttributeMaxDynamicSharedMemorySize, SM1);
    cudaFuncSetAttribute(rel_kernel<128, 2, 2, 0>, cudaFuncAttributeMaxDynamicSharedMemorySize, SM2);
    cudaFuncSetAttribute(rel_kernel<192, 3, 3, 0>, cudaFuncAttributeMaxDynamicSharedMemorySize, SM3);
    cudaFuncSetAttribute(update_kernel,            cudaFuncAttributeMaxDynamicSharedMemorySize, SMU);

    conv_all_kernel<<<(69632 + 255) / 256, 256>>>(Wi1, Wo1, Wi2, Wo2, Wi3, Wo3, uWi, uWo);
    zero_counts_kernel<<<(N + 255) / 256, 256>>>(N);
    count_all_kernel<<<1024, 256>>>(a1, n1, a2, n2, a3, n3);

    // layer 0 — rel kernels don't need the CSR
    rel_kernel<192, 3, 3, 0><<<(m3 + 63) / 64, 256, SM3>>>(h0, 0, a3, m3, bi3, bo3, (long long)n2 * 32);

    scan_local_kernel<<<nb, 1024>>>(N);
    scan_tops_kernel<<<1, 512>>>(nb, N);
    scan_add_kernel<<<(N + 255) / 256, 256>>>(N);
    fill_all_kernel<<<1024, 256>>>(a2, n2, a3, n3);

    rel_kernel<128, 2, 2, 0><<<(m2 + 63) / 64, 256, SM2>>>(h0, 0, a2, m2, bi2, bo2, 0LL);
    rel_kernel<64, 1, 1, 1><<<(N + 63) / 64, 256, SM1>>>(h0, 0, nullptr, N, bi1, bo1, 0LL);
    agg_kernel<<<(N + 7) / 8, 256>>>(N);
    update_kernel<<<(N + 63) / 64, 256, SMU>>>(h0, 0, 1, N, ubi, ubo);

    // layer 1
    rel_kernel<192, 3, 3, 0><<<(m3 + 63) / 64, 256, SM3>>>(h0, 1, a3, m3, bi3, bo3, (long long)n2 * 32);
    rel_kernel<128, 2, 2, 0><<<(m2 + 63) / 64, 256, SM2>>>(h0, 1, a2, m2, bi2, bo2, 0LL);
    rel_kernel<64, 1, 1, 1><<<(N + 63) / 64, 256, SM1>>>(h0, 1, nullptr, N, bi1, bo1, 0LL);
    agg_kernel<<<(N + 7) / 8, 256>>>(N);
    update_kernel<<<(N + 63) / 64, 256, SMU>>>(h0, 1, 2, N, ubi, ubo);

    // readout
    bounds_kernel<<<1, 32>>>(tok, B);
    segsum_kernel<<<B, 256>>>();
    heads_kernel<<<B, 64>>>(vWi, vbi, vWo, vbo, dWi, dbi, dWo, dbo, out, B);
}

// round 16
// speedup vs baseline: 1.1010x; 1.1010x over previous
#include <cuda_runtime.h>
#include <cuda_fp16.h>
#include <math.h>
#include <stdint.h>

// ---------------- static scratch (no allocations allowed) ----------------
#define NMAX   131072
#define TMAX   1700000

__device__ unsigned g_msgsh[(size_t)TMAX * 32];  // r2|r3 messages, half2 words
__device__ unsigned g_msg1h[(size_t)NMAX * 32];  // per-node r1 messages, half2 words
__device__ int   g_colidx[TMAX];
__device__ int   g_counts[NMAX];
__device__ int   g_cnt1[NMAX];
__device__ int   g_rowptr[NMAX + 1];
__device__ int   g_cursor[NMAX];
__device__ int   g_bsum[512];
__device__ float g_hA[(size_t)NMAX * 64];
__device__ float g_hB[(size_t)NMAX * 64];
__device__ float g_maxmsg[(size_t)NMAX * 64];
__device__ int   g_bounds[257];
__device__ float g_agg[256 * 64];

// packed fp16 weights: word (k2, n) = half2{ W[2*k2][n], W[2*k2+1][n] }
__device__ unsigned g_pWi1[32 * 64],   g_pWo1[32 * 64];
__device__ unsigned g_pWi2[64 * 128],  g_pWo2[64 * 128];
__device__ unsigned g_pWi3[96 * 192],  g_pWo3[96 * 192];
__device__ unsigned g_puWi[64 * 128],  g_puWo[64 * 64];

// ---------------- math helpers ----------------
__device__ __forceinline__ float mishf(float x) {
    if (x > 20.f) return x;
    float e = __expf(x);
    float n = e * (e + 2.f);
    return x * (n / (n + 2.f));
}

__device__ __forceinline__ unsigned pack_h2(float a, float b) {
    __half2 h = __floats2half2_rn(a, b);
    return *reinterpret_cast<unsigned*>(&h);
}

__device__ __forceinline__ void unpack_h2(unsigned w, float& a, float& b) {
    __half2 h = *reinterpret_cast<__half2*>(&w);
    a = __low2float(h);
    b = __high2float(h);
}

// m16n8k16 f16 MMA, fp32 accumulate
__device__ __forceinline__ void mma16(float* c, unsigned a0, unsigned a1, unsigned a2, unsigned a3,
                                      unsigned b0, unsigned b1) {
    asm volatile(
        "mma.sync.aligned.m16n8k16.row.col.f32.f16.f16.f32 "
        "{%0,%1,%2,%3}, {%4,%5,%6,%7}, {%8,%9}, {%0,%1,%2,%3};\n"
        : "+f"(c[0]), "+f"(c[1]), "+f"(c[2]), "+f"(c[3])
        : "r"(a0), "r"(a1), "r"(a2), "r"(a3), "r"(b0), "r"(b1));
}

// ---------------- weight pre-packing (1 launch) ----------------
__device__ __forceinline__ unsigned pack_w(const float* __restrict__ W, int N, int j) {
    int k2 = j / N, n = j - k2 * N;
    return pack_h2(W[(2 * k2) * N + n], W[(2 * k2 + 1) * N + n]);
}

__global__ void conv_all_kernel(const float* __restrict__ Wi1, const float* __restrict__ Wo1,
                                const float* __restrict__ Wi2, const float* __restrict__ Wo2,
                                const float* __restrict__ Wi3, const float* __restrict__ Wo3,
                                const float* __restrict__ uWi, const float* __restrict__ uWo)
{
    int i = blockIdx.x * blockDim.x + threadIdx.x;
    if (i < 2048)            g_pWi1[i] = pack_w(Wi1, 64, i);
    else if (i < 4096)       g_pWo1[i - 2048]  = pack_w(Wo1, 64,  i - 2048);
    else if (i < 12288)      g_pWi2[i - 4096]  = pack_w(Wi2, 128, i - 4096);
    else if (i < 20480)      g_pWo2[i - 12288] = pack_w(Wo2, 128, i - 12288);
    else if (i < 38912)      g_pWi3[i - 20480] = pack_w(Wi3, 192, i - 20480);
    else if (i < 57344)      g_pWo3[i - 38912] = pack_w(Wo3, 192, i - 38912);
    else if (i < 65536)      g_puWi[i - 57344] = pack_w(uWi, 128, i - 57344);
    else if (i < 69632)      g_puWo[i - 65536] = pack_w(uWo, 64,  i - 65536);
}

// ---------------- CSR build (r2/r3 only; r1 -> multiplicity counts) ----------------
__global__ void zero_counts_kernel(int n) {
    int i = blockIdx.x * blockDim.x + threadIdx.x;
    if (i < n) { g_counts[i] = 0; g_cnt1[i] = 0; }
}

__global__ void count_all_kernel(const int* __restrict__ a1, int n1,
                                 const int* __restrict__ a2, int n2,
                                 const int* __restrict__ a3, int n3)
{
    int total = n1 + n2 + n3;
    for (int i = blockIdx.x * blockDim.x + threadIdx.x; i < total; i += gridDim.x * blockDim.x) {
        if (i < n2)            atomicAdd(&g_counts[a2[i]], 1);
        else if (i < n2 + n3)  atomicAdd(&g_counts[a3[i - n2]], 1);
        else                   atomicAdd(&g_cnt1[a1[i - n2 - n3]], 1);
    }
}

__global__ void scan_local_kernel(int n) {
    __shared__ int wsum[32];
    int i = blockIdx.x * 1024 + threadIdx.x;
    int lane = threadIdx.x & 31, wid = threadIdx.x >> 5;
    int v = (i < n) ? g_counts[i] : 0;
    int x = v;
    #pragma unroll
    for (int o = 1; o < 32; o <<= 1) {
        int y = __shfl_up_sync(0xFFFFFFFFu, x, o);
        if (lane >= o) x += y;
    }
    if (lane == 31) wsum[wid] = x;
    __syncthreads();
    if (wid == 0) {
        int s = wsum[lane];
        #pragma unroll
        for (int o = 1; o < 32; o <<= 1) {
            int y = __shfl_up_sync(0xFFFFFFFFu, s, o);
            if (lane >= o) s += y;
        }
        wsum[lane] = s;
    }
    __syncthreads();
    int excl = x - v + ((wid > 0) ? wsum[wid - 1] : 0);
    if (i < n) g_rowptr[i] = excl;
    if (threadIdx.x == 1023) g_bsum[blockIdx.x] = excl + v;
}

__global__ void scan_tops_kernel(int nb, int n) {
    __shared__ int sh[512];
    int t = threadIdx.x;
    int v = (t < nb) ? g_bsum[t] : 0;
    sh[t] = v;
    __syncthreads();
    for (int o = 1; o < 512; o <<= 1) {
        int y = (t >= o) ? sh[t - o] : 0;
        __syncthreads();
        sh[t] += y;
        __syncthreads();
    }
    if (t < nb) g_bsum[t] = sh[t] - v;
    if (t == 0) g_rowptr[n] = sh[511];
}

__global__ void scan_add_kernel(int n) {
    int i = blockIdx.x * blockDim.x + threadIdx.x;
    if (i < n) {
        int r = g_rowptr[i] + g_bsum[i >> 10];
        g_rowptr[i] = r;
        g_cursor[i] = r;
    }
}

__global__ void fill_all_kernel(const int* __restrict__ a2, int n2,
                                const int* __restrict__ a3, int n3)
{
    int total = n2 + n3;
    for (int i = blockIdx.x * blockDim.x + threadIdx.x; i < total; i += gridDim.x * blockDim.x) {
        int v = (i < n2) ? a2[i] : a3[i - n2];
        int pos = atomicAdd(&g_cursor[v], 1);
        g_colidx[pos] = i;
    }
}

// ---------------- relation MLP (FP16 MMA m16n8k16, double-buffered weight chunks) ----------------
template <int S, int A, int R, int IDENT>
__global__ void __launch_bounds__(256)
rel_kernel(const float* __restrict__ hext, int hsel,
           const int* __restrict__ atoms, int m,
           const float* __restrict__ bi, const float* __restrict__ bo,
           long long outOffW)
{
    constexpr int BM  = 64;
    constexpr int NT  = S / 32;
    constexpr int KC  = S / 16;
    constexpr int XST = S / 2 + 4;
    constexpr int WST = S + 8;
    constexpr int S4  = S / 4;
    constexpr int PF4 = (2 * S + 255) / 256;

    extern __shared__ unsigned sm[];
    unsigned* xs  = sm;
    unsigned* ws0 = xs + BM * XST;
    unsigned* ws1 = ws0 + 8 * WST;
    int* sidx = (int*)(ws1 + 8 * WST);

    const unsigned* Wip = (R == 1) ? g_pWi1 : (R == 2) ? g_pWi2 : g_pWi3;
    const unsigned* Wop = (R == 1) ? g_pWo1 : (R == 2) ? g_pWo2 : g_pWo3;
    const uint4* Wi4 = (const uint4*)Wip;
    const uint4* Wo4 = (const uint4*)Wop;

    const float* h = (hsel == 0) ? hext : ((hsel == 1) ? g_hA : g_hB);
    unsigned* outw = IDENT ? g_msg1h : (g_msgsh + outOffW);

    const int tid  = threadIdx.x;
    const int lane = tid & 31;
    const int warp = tid >> 5;
    const int rg   = warp & 1;
    const int cg   = warp >> 1;
    const int gid  = lane >> 2;
    const int ctg  = lane & 3;
    const int row0 = blockIdx.x * BM;

    if (!IDENT) {
        if (tid < BM * A) {
            int t = row0 * A + tid;
            sidx[tid] = (t < m * A) ? atoms[t] : 0;
        }
        __syncthreads();
    }

    const float4* h4 = (const float4*)h;
    #pragma unroll
    for (int v = 0; v < S / 16; v++) {
        int u = tid + v * 256;
        int r = u / S4;
        int rem = u - r * S4;
        int node;
        if (IDENT) { node = row0 + r; if (node >= m) node = 0; }
        else       { node = sidx[r * A + (rem >> 4)]; }
        float4 val = h4[(size_t)node * 16 + (rem & 15)];
        ((uint2*)xs)[r * (XST / 2) + rem] = make_uint2(pack_h2(val.x, val.y), pack_h2(val.z, val.w));
    }

    {
        uint4 pre[PF4];
        #pragma unroll
        for (int v = 0; v < PF4; v++) {
            int u = tid + v * 256;
            if (u < 2 * S) pre[v] = Wi4[u];
        }
        #pragma unroll
        for (int v = 0; v < PF4; v++) {
            int u = tid + v * 256;
            if (u < 2 * S) {
                int rr = u / S4, c4 = u - rr * S4;
                ((uint4*)ws0)[rr * (WST / 4) + c4] = pre[v];
            }
        }
    }
    __syncthreads();

    float acc[2][NT][4];
    #pragma unroll
    for (int mt = 0; mt < 2; mt++)
        #pragma unroll
        for (int nt = 0; nt < NT; nt++)
            #pragma unroll
            for (int q = 0; q < 4; q++) acc[mt][nt][q] = 0.f;

    const int rb = rg * 32 + gid;
    const int cb = cg * (S / 4);

    unsigned* cur = ws0;
    unsigned* nxt = ws1;

    for (int kc = 0; kc < KC; kc++) {
        uint4 pre[PF4];
        if (kc + 1 < KC) {
            #pragma unroll
            for (int v = 0; v < PF4; v++) {
                int u = tid + v * 256;
                if (u < 2 * S) pre[v] = Wi4[(kc + 1) * 2 * S + u];
            }
        }
        {
            int acol = kc * 8 + ctg;
            unsigned a[2][4];
            #pragma unroll
            for (int mt = 0; mt < 2; mt++) {
                const unsigned* ap = xs + (rb + mt * 16) * XST + acol;
                a[mt][0] = ap[0];
                a[mt][1] = ap[8 * XST];
                a[mt][2] = ap[4];
                a[mt][3] = ap[8 * XST + 4];
            }
            #pragma unroll
            for (int nt = 0; nt < NT; nt++) {
                int bcol = cb + nt * 8 + gid;
                unsigned b0 = cur[ctg * WST + bcol];
                unsigned b1 = cur[(ctg + 4) * WST + bcol];
                mma16(acc[0][nt], a[0][0], a[0][1], a[0][2], a[0][3], b0, b1);
                mma16(acc[1][nt], a[1][0], a[1][1], a[1][2], a[1][3], b0, b1);
            }
        }
        if (kc + 1 < KC) {
            #pragma unroll
            for (int v = 0; v < PF4; v++) {
                int u = tid + v * 256;
                if (u < 2 * S) {
                    int rr = u / S4, c4 = u - rr * S4;
                    ((uint4*)nxt)[rr * (WST / 4) + c4] = pre[v];
                }
            }
        }
        __syncthreads();
        unsigned* tmp = cur; cur = nxt; nxt = tmp;
    }

    #pragma unroll
    for (int mt = 0; mt < 2; mt++) {
        int rA = rg * 32 + mt * 16 + gid;
        #pragma unroll
        for (int nt = 0; nt < NT; nt++) {
            int c0 = cb + nt * 8 + 2 * ctg;
            int wc = (cb >> 1) + nt * 4 + ctg;
            float bi0 = __ldg(&bi[c0]), bi1 = __ldg(&bi[c0 + 1]);
            float bo0 = __ldg(&bo[c0]), bo1 = __ldg(&bo[c0 + 1]);
            unsigned* p0 = &xs[rA * XST + wc];
            unsigned* p1 = &xs[(rA + 8) * XST + wc];
            float x00, x01, x10, x11;
            unpack_h2(*p0, x00, x01);
            unpack_h2(*p1, x10, x11);
            *p0 = pack_h2(mishf(acc[mt][nt][0] + bi0), mishf(acc[mt][nt][1] + bi1));
            *p1 = pack_h2(mishf(acc[mt][nt][2] + bi0), mishf(acc[mt][nt][3] + bi1));
            acc[mt][nt][0] = x00 + bo0;
            acc[mt][nt][1] = x01 + bo1;
            acc[mt][nt][2] = x10 + bo0;
            acc[mt][nt][3] = x11 + bo1;
        }
    }

    {
        uint4 pre[PF4];
        #pragma unroll
        for (int v = 0; v < PF4; v++) {
            int u = tid + v * 256;
            if (u < 2 * S) pre[v] = Wo4[u];
        }
        #pragma unroll
        for (int v = 0; v < PF4; v++) {
            int u = tid + v * 256;
            if (u < 2 * S) {
                int rr = u / S4, c4 = u - rr * S4;
                ((uint4*)ws0)[rr * (WST / 4) + c4] = pre[v];
            }
        }
    }
    __syncthreads();

    cur = ws0; nxt = ws1;
    for (int kc = 0; kc < KC; kc++) {
        uint4 pre[PF4];
        if (kc + 1 < KC) {
            #pragma unroll
            for (int v = 0; v < PF4; v++) {
                int u = tid + v * 256;
                if (u < 2 * S) pre[v] = Wo4[(kc + 1) * 2 * S + u];
            }
        }
        {
            int acol = kc * 8 + ctg;
            unsigned a[2][4];
            #pragma unroll
            for (int mt = 0; mt < 2; mt++) {
                const unsigned* ap = xs + (rb + mt * 16) * XST + acol;
                a[mt][0] = ap[0];
                a[mt][1] = ap[8 * XST];
                a[mt][2] = ap[4];
                a[mt][3] = ap[8 * XST + 4];
            }
            #pragma unroll
            for (int nt = 0; nt < NT; nt++) {
                int bcol = cb + nt * 8 + gid;
                unsigned b0 = cur[ctg * WST + bcol];
                unsigned b1 = cur[(ctg + 4) * WST + bcol];
                mma16(acc[0][nt], a[0][0], a[0][1], a[0][2], a[0][3], b0, b1);
                mma16(acc[1][nt], a[1][0], a[1][1], a[1][2], a[1][3], b0, b1);
            }
        }
        if (kc + 1 < KC) {
            #pragma unroll
            for (int v = 0; v < PF4; v++) {
                int u = tid + v * 256;
                if (u < 2 * S) {
                    int rr = u / S4, c4 = u - rr * S4;
                    ((uint4*)nxt)[rr * (WST / 4) + c4] = pre[v];
                }
            }
        }
        __syncthreads();
        unsigned* tmp = cur; cur = nxt; nxt = tmp;
    }

    #pragma unroll
    for (int mt = 0; mt < 2; mt++) {
        int rA = row0 + rg * 32 + mt * 16 + gid;
        #pragma unroll
        for (int nt = 0; nt < NT; nt++) {
            int wc = (cb >> 1) + nt * 4 + ctg;
            if (rA < m)
                __stcs(&outw[(size_t)rA * (S / 2) + wc], pack_h2(acc[mt][nt][0], acc[mt][nt][1]));
            if (rA + 8 < m)
                __stcs(&outw[(size_t)(rA + 8) * (S / 2) + wc], pack_h2(acc[mt][nt][2], acc[mt][nt][3]));
        }
    }
}

// ---------------- smooth-max aggregation: two-pass packed fp16 ----------------
__global__ void agg_kernel(int n) {
    int w = (blockIdx.x * blockDim.x + threadIdx.x) >> 5;
    if (w >= n) return;
    int lane = threadIdx.x & 31;
    int s = g_rowptr[w], e = g_rowptr[w + 1];
    int k = g_cnt1[w];

    const float inv12 = 1.f / 12.f;

    if (s == e && k == 0) {
        float r = __logf(1e-16f) * inv12;
        *(float2*)&g_maxmsg[(size_t)w * 64 + 2 * lane] = make_float2(r, r);
        return;
    }

    __half2 mh = __float2half2_rn(-65504.f);
    for (int i = s; i < e; i++) {
        int c = __ldg(&g_colidx[i]);
        unsigned wv = __ldg(&g_msgsh[(size_t)c * 32 + lane]);
        mh = __hmax2(mh, *(__half2*)&wv);
    }
    unsigned w1v = 0;
    if (k > 0) {
        w1v = g_msg1h[(size_t)w * 32 + lane];
        mh = __hmax2(mh, *(__half2*)&w1v);
    }

    const __half2 K2 = __float2half2_rn(17.3123405f);
    float s1a = 0.f, s1b = 0.f, s2a = 0.f, s2b = 0.f;
    int i = s;
    for (; i + 2 <= e; i += 2) {
        int c0 = __ldg(&g_colidx[i]);
        int c1 = __ldg(&g_colidx[i + 1]);
        unsigned v0 = __ldcs(&g_msgsh[(size_t)c0 * 32 + lane]);
        unsigned v1 = __ldcs(&g_msgsh[(size_t)c1 * 32 + lane]);
        __half2 e0 = h2exp2(__hmul2(__hsub2(*(__half2*)&v0, mh), K2));
        __half2 e1 = h2exp2(__hmul2(__hsub2(*(__half2*)&v1, mh), K2));
        float2 f0 = __half22float2(e0);
        float2 f1 = __half22float2(e1);
        s1a += f0.x; s2a += f0.y;
        s1b += f1.x; s2b += f1.y;
    }
    if (i < e) {
        int c0 = __ldg(&g_colidx[i]);
        unsigned v0 = __ldcs(&g_msgsh[(size_t)c0 * 32 + lane]);
        __half2 e0 = h2exp2(__hmul2(__hsub2(*(__half2*)&v0, mh), K2));
        float2 f0 = __half22float2(e0);
        s1a += f0.x; s2a += f0.y;
    }

    float m1 = __low2float(mh), m2 = __high2float(mh);
    float s1 = s1a + s1b, s2 = s2a + s2b;

    if (k > 0) {
        float kf = (float)k;
        float y1, y2;
        unpack_h2(w1v, y1, y2);
        s1 += kf * exp2f(17.3123405f * (y1 - m1));
        s2 += kf * exp2f(17.3123405f * (y2 - m2));
    }

    float r1v = __logf(1e-16f + s1) * inv12 + m1;
    float r2v = __logf(1e-16f + s2) * inv12 + m2;
    *(float2*)&g_maxmsg[(size_t)w * 64 + 2 * lane] = make_float2(r1v, r2v);
}

// ---------------- update MLP (FP16 MMA, double-buffered chunks) ----------------
__global__ void __launch_bounds__(256)
update_kernel(const float* __restrict__ hext, int hinsel, int houtsel, int n,
              const float* __restrict__ bi, const float* __restrict__ bo)
{
    constexpr int XST = 68;
    constexpr int WST = 136;
    extern __shared__ unsigned sm[];
    unsigned* xs  = sm;
    unsigned* ws0 = xs + 64 * XST;
    unsigned* ws1 = ws0 + 8 * WST;

    const float* hin = (hinsel == 0) ? hext : ((hinsel == 1) ? g_hA : g_hB);
    float* hout = (houtsel == 1) ? g_hA : g_hB;

    const uint4* Wi4 = (const uint4*)g_puWi;
    const uint4* Wo4 = (const uint4*)g_puWo;

    const int tid  = threadIdx.x;
    const int lane = tid & 31;
    const int warp = tid >> 5;
    const int rg   = warp & 1;
    const int cg   = warp >> 1;
    const int gid  = lane >> 2;
    const int ctg  = lane & 3;
    const int row0 = blockIdx.x * 64;
    const int rb = rg * 32 + gid;

    const float4* h4 = (const float4*)hin;
    const float4* mm4 = (const float4*)g_maxmsg;
    #pragma unroll
    for (int v = 0; v < 8; v++) {
        int u = tid + v * 256;
        int r = u >> 5, c4 = u & 31;
        float4 val = (c4 < 16) ? mm4[(size_t)(row0 + r) * 16 + c4]
                               : h4[(size_t)(row0 + r) * 16 + (c4 - 16)];
        ((uint2*)xs)[r * (XST / 2) + c4] = make_uint2(pack_h2(val.x, val.y), pack_h2(val.z, val.w));
    }
    {
        uint4 pre = Wi4[tid];
        ((uint4*)ws0)[(tid >> 5) * 34 + (tid & 31)] = pre;
    }
    __syncthreads();

    float acc[2][4][4];
    #pragma unroll
    for (int mt = 0; mt < 2; mt++)
        #pragma unroll
        for (int nt = 0; nt < 4; nt++)
            #pragma unroll
            for (int q = 0; q < 4; q++) acc[mt][nt][q] = 0.f;

    unsigned* cur = ws0;
    unsigned* nxt = ws1;
    for (int kc = 0; kc < 8; kc++) {
        uint4 pre;
        if (kc + 1 < 8) pre = Wi4[(kc + 1) * 256 + tid];
        {
            int acol = kc * 8 + ctg;
            unsigned a[2][4];
            #pragma unroll
            for (int mt = 0; mt < 2; mt++) {
                const unsigned* ap = xs + (rb + mt * 16) * XST + acol;
                a[mt][0] = ap[0];
                a[mt][1] = ap[8 * XST];
                a[mt][2] = ap[4];
                a[mt][3] = ap[8 * XST + 4];
            }
            #pragma unroll
            for (int nt = 0; nt < 4; nt++) {
                int bcol = cg * 32 + nt * 8 + gid;
                unsigned b0 = cur[ctg * WST + bcol];
                unsigned b1 = cur[(ctg + 4) * WST + bcol];
                mma16(acc[0][nt], a[0][0], a[0][1], a[0][2], a[0][3], b0, b1);
                mma16(acc[1][nt], a[1][0], a[1][1], a[1][2], a[1][3], b0, b1);
            }
        }
        if (kc + 1 < 8) {
            ((uint4*)nxt)[(tid >> 5) * 34 + (tid & 31)] = pre;
        }
        __syncthreads();
        unsigned* tmp = cur; cur = nxt; nxt = tmp;
    }

    float acc2[2][2][4];
    #pragma unroll
    for (int mt = 0; mt < 2; mt++) {
        int rA = rg * 32 + mt * 16 + gid;
        #pragma unroll
        for (int nt = 0; nt < 2; nt++) {
            int c0 = cg * 16 + nt * 8 + 2 * ctg;
            int wc = 32 + cg * 8 + nt * 4 + ctg;
            float bo0 = __ldg(&bo[c0]), bo1 = __ldg(&bo[c0 + 1]);
            float x00, x01, x10, x11;
            unpack_h2(xs[rA * XST + wc], x00, x01);
            unpack_h2(xs[(rA + 8) * XST + wc], x10, x11);
            acc2[mt][nt][0] = x00 + bo0;
            acc2[mt][nt][1] = x01 + bo1;
            acc2[mt][nt][2] = x10 + bo0;
            acc2[mt][nt][3] = x11 + bo1;
        }
    }
    __syncthreads();

    #pragma unroll
    for (int mt = 0; mt < 2; mt++) {
        int rA = rg * 32 + mt * 16 + gid;
        #pragma unroll
        for (int nt = 0; nt < 4; nt++) {
            int c0 = cg * 32 + nt * 8 + 2 * ctg;
            int wc = cg * 16 + nt * 4 + ctg;
            float bi0 = __ldg(&bi[c0]), bi1 = __ldg(&bi[c0 + 1]);
            xs[rA * XST + wc]       = pack_h2(mishf(acc[mt][nt][0] + bi0), mishf(acc[mt][nt][1] + bi1));
            xs[(rA + 8) * XST + wc] = pack_h2(mishf(acc[mt][nt][2] + bi0), mishf(acc[mt][nt][3] + bi1));
        }
    }

    {
        uint4 preW;
        if (tid < 128) preW = Wo4[tid];
        __syncthreads();
        if (tid < 128) ((uint4*)ws0)[(tid >> 4) * 34 + (tid & 15)] = preW;
    }
    __syncthreads();

    cur = ws0; nxt = ws1;
    for (int kc = 0; kc < 8; kc++) {
        uint4 pre;
        if (kc + 1 < 8 && tid < 128) pre = Wo4[(kc + 1) * 128 + tid];
        {
            int acol = kc * 8 + ctg;
            unsigned a[2][4];
            #pragma unroll
            for (int mt = 0; mt < 2; mt++) {
                const unsigned* ap = xs + (rb + mt * 16) * XST + acol;
                a[mt][0] = ap[0];
                a[mt][1] = ap[8 * XST];
                a[mt][2] = ap[4];
                a[mt][3] = ap[8 * XST + 4];
            }
            #pragma unroll
            for (int nt = 0; nt < 2; nt++) {
                int bcol = cg * 16 + nt * 8 + gid;
                unsigned b0 = cur[ctg * WST + bcol];
                unsigned b1 = cur[(ctg + 4) * WST + bcol];
                mma16(acc2[0][nt], a[0][0], a[0][1], a[0][2], a[0][3], b0, b1);
                mma16(acc2[1][nt], a[1][0], a[1][1], a[1][2], a[1][3], b0, b1);
            }
        }
        if (kc + 1 < 8 && tid < 128) {
            ((uint4*)nxt)[(tid >> 4) * 34 + (tid & 15)] = pre;
        }
        __syncthreads();
        unsigned* tmp = cur; cur = nxt; nxt = tmp;
    }

    #pragma unroll
    for (int mt = 0; mt < 2; mt++) {
        int rA = row0 + rg * 32 + mt * 16 + gid;
        #pragma unroll
        for (int nt = 0; nt < 2; nt++) {
            int c0 = cg * 16 + nt * 8 + 2 * ctg;
            if (rA < n)
                *(float2*)&hout[(size_t)rA * 64 + c0] = make_float2(acc2[mt][nt][0], acc2[mt][nt][1]);
            if (rA + 8 < n)
                *(float2*)&hout[(size_t)(rA + 8) * 64 + c0] = make_float2(acc2[mt][nt][2], acc2[mt][nt][3]);
        }
    }
}

// ---------------- readout ----------------
__global__ void bounds_kernel(const int* __restrict__ tok, int B) {
    if (threadIdx.x == 0) {
        int c = 0;
        g_bounds[0] = 0;
        for (int i = 0; i < B; i++) { c += tok[i]; g_bounds[i + 1] = c; }
    }
}

__global__ void segsum_kernel() {
    int b = blockIdx.x;
    int s = g_bounds[b], e = g_bounds[b + 1];
    int f = threadIdx.x & 63, g = threadIdx.x >> 6;
    float a = 0.f;
    for (int r = s + g; r < e; r += 4) a += g_hB[(size_t)r * 64 + f];
    __shared__ float red[256];
    red[threadIdx.x] = a;
    __syncthreads();
    if (g == 0) g_agg[b * 64 + f] = red[f] + red[64 + f] + red[128 + f] + red[192 + f];
}

__global__ void heads_kernel(const float* __restrict__ vWi, const float* __restrict__ vbi,
                             const float* __restrict__ vWo, const float* __restrict__ vbo,
                             const float* __restrict__ dWi, const float* __restrict__ dbi,
                             const float* __restrict__ dWo, const float* __restrict__ dbo,
                             float* __restrict__ out, int B)
{
    int b = blockIdx.x, o = threadIdx.x;
    __shared__ float a[64];
    __shared__ float red[64];
    a[o] = g_agg[b * 64 + o];
    __syncthreads();

    float t = vbi[o];
    for (int i = 0; i < 64; i++) t = fmaf(a[i], vWi[i * 64 + o], t);
    red[o] = mishf(t) * vWo[o];
    __syncthreads();
    for (int s = 32; s > 0; s >>= 1) {
        if (o < s) red[o] += red[o + s];
        __syncthreads();
    }
    if (o == 0) out[b] = red[0] + vbo[0];
    __syncthreads();

    t = dbi[o];
    for (int i = 0; i < 64; i++) t = fmaf(a[i], dWi[i * 64 + o], t);
    red[o] = mishf(t) * dWo[o];
    __syncthreads();
    for (int s = 32; s > 0; s >>= 1) {
        if (o < s) red[o] += red[o + s];
        __syncthreads();
    }
    if (o == 0) out[B + b] = red[0] + dbo[0];
}

// ---------------- host launch (multi-stream fork-join, graph-capturable) ----------------
static inline int smem_rel(int S, int A) {
    return (64 * (S / 2 + 4) + 16 * (S + 8)) * 4 + 64 * A * 4;
}

extern "C" void kernel_launch(void* const* d_in, const int* in_sizes, int n_in,
                              void* d_out, int out_size)
{
    if (n_in < 29) return;
    const float* h0  = (const float*)d_in[0];
    const int*   a1  = (const int*)d_in[1];  int n1 = in_sizes[1];
    const int*   a2  = (const int*)d_in[2];  int n2 = in_sizes[2];
    const int*   a3  = (const int*)d_in[3];  int n3 = in_sizes[3];
    const int*   tok = (const int*)d_in[4];  int B  = in_sizes[4];
    const float* Wi1 = (const float*)d_in[5],  *bi1 = (const float*)d_in[6];
    const float* Wo1 = (const float*)d_in[7],  *bo1 = (const float*)d_in[8];
    const float* Wi2 = (const float*)d_in[9],  *bi2 = (const float*)d_in[10];
    const float* Wo2 = (const float*)d_in[11], *bo2 = (const float*)d_in[12];
    const float* Wi3 = (const float*)d_in[13], *bi3 = (const float*)d_in[14];
    const float* Wo3 = (const float*)d_in[15], *bo3 = (const float*)d_in[16];
    const float* uWi = (const float*)d_in[17], *ubi = (const float*)d_in[18];
    const float* uWo = (const float*)d_in[19], *ubo = (const float*)d_in[20];
    const float* vWi = (const float*)d_in[21], *vbi = (const float*)d_in[22];
    const float* vWo = (const float*)d_in[23], *vbo = (const float*)d_in[24];
    const float* dWi = (const float*)d_in[25], *dbi = (const float*)d_in[26];
    const float* dWo = (const float*)d_in[27], *dbo = (const float*)d_in[28];
    float* out = (float*)d_out;

    int N = in_sizes[0] / 64;
    int m2 = n2 / 2, m3 = n3 / 3;
    int nb = (N + 1023) / 1024;

    const int SM1 = smem_rel(64, 1);
    const int SM2 = smem_rel(128, 2);
    const int SM3 = smem_rel(192, 3);
    const int SMU = (64 * 68 + 16 * 136) * 4;

    // lazy one-time init of streams/events (first call = correctness run, before capture)
    static cudaStream_t s1 = nullptr, s2 = nullptr;
    static cudaEvent_t evF, evConv, evCSR, evS2a, evU0, evS2b;
    if (s1 == nullptr) {
        cudaStreamCreateWithFlags(&s1, cudaStreamNonBlocking);
        cudaStreamCreateWithFlags(&s2, cudaStreamNonBlocking);
        cudaEventCreateWithFlags(&evF,    cudaEventDisableTiming);
        cudaEventCreateWithFlags(&evConv, cudaEventDisableTiming);
        cudaEventCreateWithFlags(&evCSR,  cudaEventDisableTiming);
        cudaEventCreateWithFlags(&evS2a,  cudaEventDisableTiming);
        cudaEventCreateWithFlags(&evU0,   cudaEventDisableTiming);
        cudaEventCreateWithFlags(&evS2b,  cudaEventDisableTiming);

        cudaFuncSetAttribute(rel_kernel<64, 1, 1, 1>,  cudaFuncAttributeMaxDynamicSharedMemorySize, SM1);
        cudaFuncSetAttribute(rel_kernel<128, 2, 2, 0>, cudaFuncAttributeMaxDynamicSharedMemorySize, SM2);
        cudaFuncSetAttribute(rel_kernel<192, 3, 3, 0>, cudaFuncAttributeMaxDynamicSharedMemorySize, SM3);
        cudaFuncSetAttribute(update_kernel,            cudaFuncAttributeMaxDynamicSharedMemorySize, SMU);
    }

    // fork: s1 runs the CSR chain (independent of conv/weights)
    cudaEventRecord(evF, 0);
    cudaStreamWaitEvent(s1, evF, 0);
    zero_counts_kernel<<<(N + 255) / 256, 256, 0, s1>>>(N);
    count_all_kernel<<<1024, 256, 0, s1>>>(a1, n1, a2, n2, a3, n3);
    scan_local_kernel<<<nb, 1024, 0, s1>>>(N);
    scan_tops_kernel<<<1, 512, 0, s1>>>(nb, N);
    scan_add_kernel<<<(N + 255) / 256, 256, 0, s1>>>(N);
    fill_all_kernel<<<1024, 256, 0, s1>>>(a2, n2, a3, n3);
    cudaEventRecord(evCSR, s1);

    // stream 0: conv, then rel192(L0); s2: rel128+rel64(L0) after conv
    conv_all_kernel<<<(69632 + 255) / 256, 256>>>(Wi1, Wo1, Wi2, Wo2, Wi3, Wo3, uWi, uWo);
    cudaEventRecord(evConv, 0);
    cudaStreamWaitEvent(s2, evConv, 0);
    rel_kernel<128, 2, 2, 0><<<(m2 + 63) / 64, 256, SM2, s2>>>(h0, 0, a2, m2, bi2, bo2, 0LL);
    rel_kernel<64, 1, 1, 1><<<(N + 63) / 64, 256, SM1, s2>>>(h0, 0, nullptr, N, bi1, bo1, 0LL);
    cudaEventRecord(evS2a, s2);

    rel_kernel<192, 3, 3, 0><<<(m3 + 63) / 64, 256, SM3>>>(h0, 0, a3, m3, bi3, bo3, (long long)n2 * 32);

    // join for agg(L0)
    cudaStreamWaitEvent(0, evCSR, 0);
    cudaStreamWaitEvent(0, evS2a, 0);
    agg_kernel<<<(N + 7) / 8, 256>>>(N);
    update_kernel<<<(N + 63) / 64, 256, SMU>>>(h0, 0, 1, N, ubi, ubo);

    // layer 1 fork
    cudaEventRecord(evU0, 0);
    cudaStreamWaitEvent(s2, evU0, 0);
    rel_kernel<128, 2, 2, 0><<<(m2 + 63) / 64, 256, SM2, s2>>>(h0, 1, a2, m2, bi2, bo2, 0LL);
    rel_kernel<64, 1, 1, 1><<<(N + 63) / 64, 256, SM1, s2>>>(h0, 1, nullptr, N, bi1, bo1, 0LL);
    cudaEventRecord(evS2b, s2);

    rel_kernel<192, 3, 3, 0><<<(m3 + 63) / 64, 256, SM3>>>(h0, 1, a3, m3, bi3, bo3, (long long)n2 * 32);

    cudaStreamWaitEvent(0, evS2b, 0);
    agg_kernel<<<(N + 7) / 8, 256>>>(N);
    update_kernel<<<(N + 63) / 64, 256, SMU>>>(h0, 1, 2, N, ubi, ubo);

    // readout
    bounds_kernel<<<1, 32>>>(tok, B);
    segsum_kernel<<<B, 256>>>();
    heads_kernel<<<B, 64>>>(vWi, vbi, vWo, vbo, dWi, dbi, dWo, dbo, out, B);
}